// round 2
// baseline (speedup 1.0000x reference)
#include <cuda_runtime.h>
#include <math.h>

#define BATCH   2
#define SEQLEN  1024
#define DMODEL  1024
#define DINNER  2048
#define NSTATE  16
#define BL      (BATCH*SEQLEN)      // 2048 rows
#define XPROJ_ROWS 33               // 1 dt + 16 B + 16 C

// ---------------- scratch (no allocs allowed) ----------------
__device__ float g_xz[(size_t)BL * 2 * DINNER];   // 32 MB  [bl][4096]
__device__ float g_xc[(size_t)BL * DINNER];       // 16 MB
__device__ float g_xp[(size_t)BL * XPROJ_ROWS];   // 270 KB
__device__ float g_dt[(size_t)BL * DINNER];       // 16 MB
__device__ float g_yg[(size_t)BL * DINNER];       // 16 MB

// ---------------- SGEMM: C[M,N] = A[M,K] * B[N,K]^T ----------------
// Row-major A[M,K], B[N,K], C[M,N]. Requires M%128==0, N%128==0, K%8==0.
// 128x128 tile, BK=8, 256 threads, 8x8 per-thread microtile.
__global__ __launch_bounds__(256) void sgemm_nt(const float* __restrict__ A,
                                                const float* __restrict__ B,
                                                float* __restrict__ C,
                                                int M, int N, int K) {
    __shared__ __align__(16) float As[8][128];
    __shared__ __align__(16) float Bs[8][128];

    const int t  = threadIdx.x;
    const int tx = t & 15;          // 0..15  (N direction)
    const int ty = t >> 4;          // 0..15  (M direction)
    const int rowBase = blockIdx.y * 128;
    const int colBase = blockIdx.x * 128;

    const int lr = t >> 1;          // 0..127 row within tile
    const int lc = (t & 1) * 4;     // 0 or 4

    const float* Ag = A + (size_t)(rowBase + lr) * K + lc;
    const float* Bg = B + (size_t)(colBase + lr) * K + lc;

    float acc[8][8];
#pragma unroll
    for (int i = 0; i < 8; i++)
#pragma unroll
        for (int j = 0; j < 8; j++) acc[i][j] = 0.f;

    for (int kt = 0; kt < K; kt += 8) {
        float4 av = *(const float4*)(Ag + kt);
        float4 bv = *(const float4*)(Bg + kt);
        As[lc + 0][lr] = av.x; As[lc + 1][lr] = av.y;
        As[lc + 2][lr] = av.z; As[lc + 3][lr] = av.w;
        Bs[lc + 0][lr] = bv.x; Bs[lc + 1][lr] = bv.y;
        Bs[lc + 2][lr] = bv.z; Bs[lc + 3][lr] = bv.w;
        __syncthreads();

#pragma unroll
        for (int kk = 0; kk < 8; kk++) {
            float a[8], b[8];
            *(float4*)&a[0] = *(const float4*)&As[kk][ty * 8];
            *(float4*)&a[4] = *(const float4*)&As[kk][ty * 8 + 4];
            *(float4*)&b[0] = *(const float4*)&Bs[kk][tx * 8];
            *(float4*)&b[4] = *(const float4*)&Bs[kk][tx * 8 + 4];
#pragma unroll
            for (int i = 0; i < 8; i++)
#pragma unroll
                for (int j = 0; j < 8; j++)
                    acc[i][j] = fmaf(a[i], b[j], acc[i][j]);
        }
        __syncthreads();
    }

#pragma unroll
    for (int i = 0; i < 8; i++) {
        float* Cp = C + (size_t)(rowBase + ty * 8 + i) * N + colBase + tx * 8;
        float4 v0 = make_float4(acc[i][0], acc[i][1], acc[i][2], acc[i][3]);
        float4 v1 = make_float4(acc[i][4], acc[i][5], acc[i][6], acc[i][7]);
        *(float4*)Cp       = v0;
        *(float4*)(Cp + 4) = v1;
    }
}

// ---------------- causal conv (width 4) + SiLU ----------------
__global__ __launch_bounds__(256) void conv_silu_kernel(const float* __restrict__ conv_w,
                                                        const float* __restrict__ conv_b) {
    int idx = blockIdx.x * 256 + threadIdx.x;
    if (idx >= BL * DINNER) return;
    int d  = idx & (DINNER - 1);
    int bl = idx >> 11;
    int l  = bl & (SEQLEN - 1);

    float acc = conv_b[d];
#pragma unroll
    for (int k = 0; k < 4; k++) {
        int ls = l + k - 3;
        if (ls >= 0)
            acc = fmaf(conv_w[d * 4 + k],
                       g_xz[(size_t)(bl + k - 3) * (2 * DINNER) + d], acc);
    }
    // silu
    float sig = 1.f / (1.f + expf(-acc));
    g_xc[idx] = acc * sig;
}

// ---------------- x_proj: xp[bl][j] = dot(xc[bl][:], W[j][:]) ----------------
// 4 rows per block to reuse the weight reads; 128 threads = 4 warps.
__global__ __launch_bounds__(128) void xproj_kernel(const float* __restrict__ W) {
    __shared__ float sx[4][DINNER];   // 32 KB
    const int bl0 = blockIdx.x * 4;
    for (int i = threadIdx.x; i < 4 * DINNER; i += 128)
        sx[i >> 11][i & (DINNER - 1)] = g_xc[(size_t)bl0 * DINNER + i];
    __syncthreads();

    const int warp = threadIdx.x >> 5, lane = threadIdx.x & 31;
    for (int j = warp; j < XPROJ_ROWS; j += 4) {
        const float* wr = W + (size_t)j * DINNER;
        float s0 = 0.f, s1 = 0.f, s2 = 0.f, s3 = 0.f;
        for (int i = lane; i < DINNER; i += 32) {
            float w = wr[i];
            s0 = fmaf(sx[0][i], w, s0);
            s1 = fmaf(sx[1][i], w, s1);
            s2 = fmaf(sx[2][i], w, s2);
            s3 = fmaf(sx[3][i], w, s3);
        }
#pragma unroll
        for (int o = 16; o; o >>= 1) {
            s0 += __shfl_xor_sync(0xffffffffu, s0, o);
            s1 += __shfl_xor_sync(0xffffffffu, s1, o);
            s2 += __shfl_xor_sync(0xffffffffu, s2, o);
            s3 += __shfl_xor_sync(0xffffffffu, s3, o);
        }
        if (lane == 0) {
            g_xp[(size_t)(bl0 + 0) * XPROJ_ROWS + j] = s0;
            g_xp[(size_t)(bl0 + 1) * XPROJ_ROWS + j] = s1;
            g_xp[(size_t)(bl0 + 2) * XPROJ_ROWS + j] = s2;
            g_xp[(size_t)(bl0 + 3) * XPROJ_ROWS + j] = s3;
        }
    }
}

// ---------------- dt = softplus(dt_r * w + b), hoisted out of the scan ----------------
__global__ __launch_bounds__(256) void dt_kernel(const float* __restrict__ dtw,
                                                 const float* __restrict__ dtb) {
    int idx = blockIdx.x * 256 + threadIdx.x;
    if (idx >= BL * DINNER) return;
    int d  = idx & (DINNER - 1);
    int bl = idx >> 11;
    float x = fmaf(g_xp[(size_t)bl * XPROJ_ROWS], dtw[d], dtb[d]);
    // numerically-stable softplus
    float sp = fmaxf(x, 0.f) + log1pf(expf(-fabsf(x)));
    g_dt[idx] = sp;
}

// ---------------- selective scan ----------------
// One warp handles 2 (b,d) channels: group = lane>>4, n = lane&15.
// h kept in a register per lane; y = sum_n h*C via 16-lane shuffle reduce.
// Also fuses +xc*D, the silu(z) gate, and writes yg.
__global__ __launch_bounds__(256) void scan_kernel(const float* __restrict__ A_log,
                                                   const float* __restrict__ D_param) {
    const int warp_global = blockIdx.x * 8 + (threadIdx.x >> 5);
    const int lane  = threadIdx.x & 31;
    const int group = lane >> 4;
    const int n     = lane & 15;
    const int p2 = warp_global * 2;
    const int d  = (p2 & (DINNER - 1)) + group;
    const int b  = p2 >> 11;

    const float Acoef = -expf(A_log[d * NSTATE + n]);
    const float Dp    = D_param[d];

    const float* xpb = g_xp + (size_t)b * SEQLEN * XPROJ_ROWS;
    const float* dtp = g_dt + (size_t)b * SEQLEN * DINNER + d;
    const float* xcp = g_xc + (size_t)b * SEQLEN * DINNER + d;
    const float* zp  = g_xz + (size_t)b * SEQLEN * (2 * DINNER) + DINNER + d;
    float*       ygp = g_yg + (size_t)b * SEQLEN * DINNER + d;

    float h = 0.f;
    for (int t = 0; t < SEQLEN; t++) {
        const float dtv = dtp[(size_t)t * DINNER];
        const float xcv = xcp[(size_t)t * DINNER];
        const float* xpr = xpb + (size_t)t * XPROJ_ROWS;
        const float Bv = xpr[1 + n];
        const float Cv = xpr[1 + NSTATE + n];

        const float dA = __expf(dtv * Acoef);
        h = fmaf(dA, h, dtv * xcv * Bv);

        float prod = h * Cv;
        prod += __shfl_xor_sync(0xffffffffu, prod, 8);
        prod += __shfl_xor_sync(0xffffffffu, prod, 4);
        prod += __shfl_xor_sync(0xffffffffu, prod, 2);
        prod += __shfl_xor_sync(0xffffffffu, prod, 1);

        if (n == 0) {
            float y = prod + xcv * Dp;
            float z = zp[(size_t)t * (2 * DINNER)];
            float sig = 1.f / (1.f + __expf(-z));
            ygp[(size_t)t * DINNER] = y * (z * sig);
        }
    }
}

// ---------------- launch ----------------
extern "C" void kernel_launch(void* const* d_in, const int* in_sizes, int n_in,
                              void* d_out, int out_size) {
    const float* x          = (const float*)d_in[0];
    const float* in_proj_w  = (const float*)d_in[1];
    const float* conv_w     = (const float*)d_in[2];
    const float* conv_b     = (const float*)d_in[3];
    const float* x_proj_w   = (const float*)d_in[4];
    const float* dt_proj_w  = (const float*)d_in[5];
    const float* dt_proj_b  = (const float*)d_in[6];
    const float* A_log      = (const float*)d_in[7];
    const float* D_param    = (const float*)d_in[8];
    const float* out_proj_w = (const float*)d_in[9];
    float* out = (float*)d_out;

    float *xz_p = nullptr, *yg_p = nullptr;
    cudaGetSymbolAddress((void**)&xz_p, g_xz);
    cudaGetSymbolAddress((void**)&yg_p, g_yg);

    // 1) xz = x @ in_proj_w^T        [2048,1024] x [4096,1024]^T
    sgemm_nt<<<dim3((2 * DINNER) / 128, BL / 128), 256>>>(
        x, in_proj_w, xz_p, BL, 2 * DINNER, DMODEL);

    // 2) causal conv + silu -> xc
    conv_silu_kernel<<<(BL * DINNER + 255) / 256, 256>>>(conv_w, conv_b);

    // 3) xp = xc @ x_proj_w^T (skinny N=33)
    xproj_kernel<<<BL / 4, 128>>>(x_proj_w);

    // 4) dt = softplus(...)
    dt_kernel<<<(BL * DINNER + 255) / 256, 256>>>(dt_proj_w, dt_proj_b);

    // 5) selective scan + D skip + silu(z) gate -> yg
    scan_kernel<<<(BATCH * DINNER / 2) / 8, 256>>>(A_log, D_param);

    // 6) out = yg @ out_proj_w^T     [2048,2048] x [1024,2048]^T
    sgemm_nt<<<dim3(DMODEL / 128, BL / 128), 256>>>(
        yg_p, out_proj_w, out, BL, DMODEL, DINNER);
}

// round 3
// speedup vs baseline: 1.4998x; 1.4998x over previous
#include <cuda_runtime.h>
#include <math.h>

#define BATCH   2
#define SEQLEN  1024
#define DMODEL  1024
#define DINNER  2048
#define NSTATE  16
#define BL      (BATCH*SEQLEN)      // 2048 rows
#define XPROJ_ROWS 33               // 1 dt + 16 B + 16 C

// ---------------- scratch (no allocs allowed) ----------------
__device__ float g_xz[(size_t)BL * 2 * DINNER];   // 32 MB  [bl][4096]
__device__ float g_xc[(size_t)BL * DINNER];       // 16 MB
__device__ float g_xp[(size_t)BL * XPROJ_ROWS];   // 270 KB
__device__ float g_dt[(size_t)BL * DINNER];       // 16 MB
__device__ float g_yg[(size_t)BL * DINNER];       // 16 MB

// ================= TF32 tensor-core GEMM =================
// C[M,N] = A[M,K] * B[N,K]^T, all row-major fp32, TF32 mma with RNA rounding.
// M%128==0, N%128==0, K%32==0.
// 128x128 CTA tile, BK=32, 256 threads (8 warps in 2x4), warp tile 64x32.
// Smem pitch 36 floats -> fragment reads (bank = 4g+tk) conflict-free.
#define GPITCH 36
#define GBUF   (128 * GPITCH * 2)   // floats per double-buffer slot (A+B)
#define GSMEM  (2 * GBUF * 4)       // bytes of dynamic smem

__device__ __forceinline__ unsigned f2tf32(float x) {
    unsigned r;
    asm("cvt.rna.tf32.f32 %0, %1;" : "=r"(r) : "f"(x));
    return r;
}

__device__ __forceinline__ void mma_tf32(float* c, const unsigned* a, const unsigned* b) {
    asm volatile(
        "mma.sync.aligned.m16n8k8.row.col.f32.tf32.tf32.f32 "
        "{%0,%1,%2,%3}, {%4,%5,%6,%7}, {%8,%9}, {%0,%1,%2,%3};\n"
        : "+f"(c[0]), "+f"(c[1]), "+f"(c[2]), "+f"(c[3])
        : "r"(a[0]), "r"(a[1]), "r"(a[2]), "r"(a[3]), "r"(b[0]), "r"(b[1]));
}

__device__ __forceinline__ void sts_cvt4(float* dst, float4 v) {
    float4 w;
    w.x = __uint_as_float(f2tf32(v.x));
    w.y = __uint_as_float(f2tf32(v.y));
    w.z = __uint_as_float(f2tf32(v.z));
    w.w = __uint_as_float(f2tf32(v.w));
    *(float4*)dst = w;
}

__global__ __launch_bounds__(256) void gemm_tf32(const float* __restrict__ A,
                                                 const float* __restrict__ B,
                                                 float* __restrict__ C,
                                                 int M, int N, int K) {
    extern __shared__ float smem[];
    const int t    = threadIdx.x;
    const int lane = t & 31;
    const int warp = t >> 5;
    const int g    = lane >> 2;     // 0..7
    const int tk   = lane & 3;      // 0..3
    const int wm   = (warp >> 2) * 64;   // 0 / 64
    const int wn   = (warp & 3) * 32;    // 0 / 32 / 64 / 96

    const int rowBase = blockIdx.y * 128;
    const int colBase = blockIdx.x * 128;
    const int ktiles  = K >> 5;

    // global loader: per pass 32 rows x 32 cols; 4 passes cover 128 rows
    const int lrow = t >> 3;          // 0..31
    const int lcol = (t & 7) * 4;     // 0..28

    const float* Ag = A + (size_t)rowBase * K;
    const float* Bg = B + (size_t)colBase * K;

    float acc[16][4];
#pragma unroll
    for (int i = 0; i < 16; i++)
#pragma unroll
        for (int j = 0; j < 4; j++) acc[i][j] = 0.f;

    // preload tile 0
    {
        float* As = smem;
        float* Bs = smem + 128 * GPITCH;
#pragma unroll
        for (int p = 0; p < 4; p++) {
            int r = lrow + p * 32;
            sts_cvt4(As + r * GPITCH + lcol, *(const float4*)(Ag + (size_t)r * K + lcol));
            sts_cvt4(Bs + r * GPITCH + lcol, *(const float4*)(Bg + (size_t)r * K + lcol));
        }
    }
    __syncthreads();

    for (int kt = 0; kt < ktiles; kt++) {
        float4 ra[4], rb[4];
        const bool more = (kt + 1 < ktiles);
        if (more) {
            const int koff = (kt + 1) << 5;
#pragma unroll
            for (int p = 0; p < 4; p++) {
                int r = lrow + p * 32;
                ra[p] = *(const float4*)(Ag + (size_t)r * K + koff + lcol);
                rb[p] = *(const float4*)(Bg + (size_t)r * K + koff + lcol);
            }
        }

        const float* As = smem + (kt & 1) * GBUF;
        const float* Bs = As + 128 * GPITCH;

#pragma unroll
        for (int ks = 0; ks < 4; ks++) {
            const int k0 = ks * 8;
            unsigned a[4][4], b[4][2];
#pragma unroll
            for (int i = 0; i < 4; i++) {
                const int m0 = wm + i * 16;
                a[i][0] = __float_as_uint(As[(m0 + g)     * GPITCH + k0 + tk]);
                a[i][1] = __float_as_uint(As[(m0 + g + 8) * GPITCH + k0 + tk]);
                a[i][2] = __float_as_uint(As[(m0 + g)     * GPITCH + k0 + tk + 4]);
                a[i][3] = __float_as_uint(As[(m0 + g + 8) * GPITCH + k0 + tk + 4]);
            }
#pragma unroll
            for (int j = 0; j < 4; j++) {
                const int n0 = wn + j * 8;
                b[j][0] = __float_as_uint(Bs[(n0 + g) * GPITCH + k0 + tk]);
                b[j][1] = __float_as_uint(Bs[(n0 + g) * GPITCH + k0 + tk + 4]);
            }
#pragma unroll
            for (int i = 0; i < 4; i++)
#pragma unroll
                for (int j = 0; j < 4; j++)
                    mma_tf32(acc[i * 4 + j], a[i], b[j]);
        }

        if (more) {
            float* Asn = smem + ((kt + 1) & 1) * GBUF;
            float* Bsn = Asn + 128 * GPITCH;
#pragma unroll
            for (int p = 0; p < 4; p++) {
                int r = lrow + p * 32;
                sts_cvt4(Asn + r * GPITCH + lcol, ra[p]);
                sts_cvt4(Bsn + r * GPITCH + lcol, rb[p]);
            }
        }
        __syncthreads();
    }

    // epilogue
#pragma unroll
    for (int i = 0; i < 4; i++) {
#pragma unroll
        for (int j = 0; j < 4; j++) {
            const float* c = acc[i * 4 + j];
            const int row0 = rowBase + wm + i * 16 + g;
            const int col  = colBase + wn + j * 8 + tk * 2;
            *(float2*)(C + (size_t)row0 * N + col)       = make_float2(c[0], c[1]);
            *(float2*)(C + (size_t)(row0 + 8) * N + col) = make_float2(c[2], c[3]);
        }
    }
}

// ---------------- causal conv (width 4) + SiLU ----------------
__global__ __launch_bounds__(256) void conv_silu_kernel(const float* __restrict__ conv_w,
                                                        const float* __restrict__ conv_b) {
    int idx = blockIdx.x * 256 + threadIdx.x;
    if (idx >= BL * DINNER) return;
    int d  = idx & (DINNER - 1);
    int bl = idx >> 11;
    int l  = bl & (SEQLEN - 1);

    float acc = conv_b[d];
#pragma unroll
    for (int k = 0; k < 4; k++) {
        int ls = l + k - 3;
        if (ls >= 0)
            acc = fmaf(conv_w[d * 4 + k],
                       g_xz[(size_t)(bl + k - 3) * (2 * DINNER) + d], acc);
    }
    float sig = 1.f / (1.f + expf(-acc));
    g_xc[idx] = acc * sig;
}

// ---------------- x_proj: xp[bl][j] = dot(xc[bl][:], W[j][:]) ----------------
__global__ __launch_bounds__(128) void xproj_kernel(const float* __restrict__ W) {
    __shared__ float sx[4][DINNER];   // 32 KB
    const int bl0 = blockIdx.x * 4;
    for (int i = threadIdx.x; i < 4 * DINNER; i += 128)
        sx[i >> 11][i & (DINNER - 1)] = g_xc[(size_t)bl0 * DINNER + i];
    __syncthreads();

    const int warp = threadIdx.x >> 5, lane = threadIdx.x & 31;
    for (int j = warp; j < XPROJ_ROWS; j += 4) {
        const float* wr = W + (size_t)j * DINNER;
        float s0 = 0.f, s1 = 0.f, s2 = 0.f, s3 = 0.f;
        for (int i = lane; i < DINNER; i += 32) {
            float w = wr[i];
            s0 = fmaf(sx[0][i], w, s0);
            s1 = fmaf(sx[1][i], w, s1);
            s2 = fmaf(sx[2][i], w, s2);
            s3 = fmaf(sx[3][i], w, s3);
        }
#pragma unroll
        for (int o = 16; o; o >>= 1) {
            s0 += __shfl_xor_sync(0xffffffffu, s0, o);
            s1 += __shfl_xor_sync(0xffffffffu, s1, o);
            s2 += __shfl_xor_sync(0xffffffffu, s2, o);
            s3 += __shfl_xor_sync(0xffffffffu, s3, o);
        }
        if (lane == 0) {
            g_xp[(size_t)(bl0 + 0) * XPROJ_ROWS + j] = s0;
            g_xp[(size_t)(bl0 + 1) * XPROJ_ROWS + j] = s1;
            g_xp[(size_t)(bl0 + 2) * XPROJ_ROWS + j] = s2;
            g_xp[(size_t)(bl0 + 3) * XPROJ_ROWS + j] = s3;
        }
    }
}

// ---------------- dt = softplus(dt_r * w + b) ----------------
__global__ __launch_bounds__(256) void dt_kernel(const float* __restrict__ dtw,
                                                 const float* __restrict__ dtb) {
    int idx = blockIdx.x * 256 + threadIdx.x;
    if (idx >= BL * DINNER) return;
    int d  = idx & (DINNER - 1);
    int bl = idx >> 11;
    float x = fmaf(g_xp[(size_t)bl * XPROJ_ROWS], dtw[d], dtb[d]);
    float sp = fmaxf(x, 0.f) + log1pf(expf(-fabsf(x)));
    g_dt[idx] = sp;
}

// ---------------- selective scan ----------------
__global__ __launch_bounds__(256) void scan_kernel(const float* __restrict__ A_log,
                                                   const float* __restrict__ D_param) {
    const int warp_global = blockIdx.x * 8 + (threadIdx.x >> 5);
    const int lane  = threadIdx.x & 31;
    const int group = lane >> 4;
    const int n     = lane & 15;
    const int p2 = warp_global * 2;
    const int d  = (p2 & (DINNER - 1)) + group;
    const int b  = p2 >> 11;

    const float Acoef = -expf(A_log[d * NSTATE + n]);
    const float Dp    = D_param[d];

    const float* xpb = g_xp + (size_t)b * SEQLEN * XPROJ_ROWS;
    const float* dtp = g_dt + (size_t)b * SEQLEN * DINNER + d;
    const float* xcp = g_xc + (size_t)b * SEQLEN * DINNER + d;
    const float* zp  = g_xz + (size_t)b * SEQLEN * (2 * DINNER) + DINNER + d;
    float*       ygp = g_yg + (size_t)b * SEQLEN * DINNER + d;

    float h = 0.f;
    for (int t = 0; t < SEQLEN; t++) {
        const float dtv = dtp[(size_t)t * DINNER];
        const float xcv = xcp[(size_t)t * DINNER];
        const float* xpr = xpb + (size_t)t * XPROJ_ROWS;
        const float Bv = xpr[1 + n];
        const float Cv = xpr[1 + NSTATE + n];

        const float dA = __expf(dtv * Acoef);
        h = fmaf(dA, h, dtv * xcv * Bv);

        float prod = h * Cv;
        prod += __shfl_xor_sync(0xffffffffu, prod, 8);
        prod += __shfl_xor_sync(0xffffffffu, prod, 4);
        prod += __shfl_xor_sync(0xffffffffu, prod, 2);
        prod += __shfl_xor_sync(0xffffffffu, prod, 1);

        if (n == 0) {
            float y = prod + xcv * Dp;
            float z = zp[(size_t)t * (2 * DINNER)];
            float sig = 1.f / (1.f + __expf(-z));
            ygp[(size_t)t * DINNER] = y * (z * sig);
        }
    }
}

// ---------------- launch ----------------
extern "C" void kernel_launch(void* const* d_in, const int* in_sizes, int n_in,
                              void* d_out, int out_size) {
    const float* x          = (const float*)d_in[0];
    const float* in_proj_w  = (const float*)d_in[1];
    const float* conv_w     = (const float*)d_in[2];
    const float* conv_b     = (const float*)d_in[3];
    const float* x_proj_w   = (const float*)d_in[4];
    const float* dt_proj_w  = (const float*)d_in[5];
    const float* dt_proj_b  = (const float*)d_in[6];
    const float* A_log      = (const float*)d_in[7];
    const float* D_param    = (const float*)d_in[8];
    const float* out_proj_w = (const float*)d_in[9];
    float* out = (float*)d_out;

    float *xz_p = nullptr, *yg_p = nullptr;
    cudaGetSymbolAddress((void**)&xz_p, g_xz);
    cudaGetSymbolAddress((void**)&yg_p, g_yg);

    static int smem_set = 0;
    if (!smem_set) {
        cudaFuncSetAttribute(gemm_tf32, cudaFuncAttributeMaxDynamicSharedMemorySize, GSMEM);
        smem_set = 1;
    }

    // 1) xz = x @ in_proj_w^T        [2048,1024] x [4096,1024]^T
    gemm_tf32<<<dim3((2 * DINNER) / 128, BL / 128), 256, GSMEM>>>(
        x, in_proj_w, xz_p, BL, 2 * DINNER, DMODEL);

    // 2) causal conv + silu -> xc
    conv_silu_kernel<<<(BL * DINNER + 255) / 256, 256>>>(conv_w, conv_b);

    // 3) xp = xc @ x_proj_w^T (skinny N=33)
    xproj_kernel<<<BL / 4, 128>>>(x_proj_w);

    // 4) dt = softplus(...)
    dt_kernel<<<(BL * DINNER + 255) / 256, 256>>>(dt_proj_w, dt_proj_b);

    // 5) selective scan + D skip + silu(z) gate -> yg
    scan_kernel<<<(BATCH * DINNER / 2) / 8, 256>>>(A_log, D_param);

    // 6) out = yg @ out_proj_w^T     [2048,2048] x [1024,2048]^T
    gemm_tf32<<<dim3(DMODEL / 128, BL / 128), 256, GSMEM>>>(
        yg_p, out_proj_w, out, BL, DMODEL, DINNER);
}